// round 1
// baseline (speedup 1.0000x reference)
#include <cuda_runtime.h>
#include <math.h>
#include <stdint.h>

// ---------------------------------------------------------------------------
// img_attention: c_img = softmax(v . tanh(Wh g* + Ws s + Wc cov)) @ g*
// with g* = X @ (W_g @ W_gs) + (b_g @ W_gs + b_gs)   [algebraic fold]
//
// Shapes: B=128, N=49 (BN=6272), G=4096, H=1024, A=1024
// ---------------------------------------------------------------------------

#define B_   128
#define N_   49
#define G_   4096
#define H_   1024
#define A_   1024
#define BN_  (B_ * N_)   // 6272

// Scratch (static device allocations — no cudaMalloc allowed)
__device__ float g_Wcomb[G_ * H_];      // 16 MB
__device__ float g_biascomb[H_];
__device__ float g_gstar[BN_ * H_];     // 25.7 MB
__device__ float g_epre[BN_ * A_];      // 25.7 MB
__device__ float g_sproj[B_ * A_];
__device__ float g_scores[BN_];

// ---------------------------------------------------------------------------
// Tiled FP32 GEMM: C[M,N] = A[M,K] @ B[K,N] (+ bias[N] if bias != nullptr)
// BM=BN=128, BK=8, 256 threads, 8x8 per thread.
// Requires M%128==0, N%128==0, K%8==0 (true for all call sites).
// ---------------------------------------------------------------------------
__global__ __launch_bounds__(256) void sgemm_kernel(
    const float* __restrict__ A, const float* __restrict__ B,
    const float* __restrict__ bias, float* __restrict__ C,
    int M, int Nn, int K)
{
    const int BM = 128, BNt = 128, BK = 8;
    __shared__ float As[BK][BM + 4];   // padded: conflict-free transposed store
    __shared__ float Bs[BK][BNt + 4];

    const int tid = threadIdx.x;
    const int bm = blockIdx.y * BM;
    const int bn = blockIdx.x * BNt;

    // A tile load: 128x8, one float4 per thread (K-contiguous), store transposed
    const int arow = tid >> 1;              // 0..127
    const int acol = (tid & 1) * 4;         // 0 or 4
    // B tile load: 8x128, one float4 per thread
    const int brow = tid >> 5;              // 0..7
    const int bcol = (tid & 31) * 4;        // 0..124

    const int tcol = (tid & 15) * 8;        // output col within tile
    const int trow = (tid >> 4) * 8;        // output row within tile

    float acc[8][8];
    #pragma unroll
    for (int i = 0; i < 8; i++)
        #pragma unroll
        for (int j = 0; j < 8; j++) acc[i][j] = 0.f;

    const float* Aptr = A + (size_t)(bm + arow) * K + acol;
    const float* Bptr = B + (size_t)brow * Nn + bn + bcol;

    for (int k0 = 0; k0 < K; k0 += BK) {
        float4 a4 = *(const float4*)Aptr;
        float4 b4 = *(const float4*)Bptr;
        As[acol + 0][arow] = a4.x;
        As[acol + 1][arow] = a4.y;
        As[acol + 2][arow] = a4.z;
        As[acol + 3][arow] = a4.w;
        *(float4*)&Bs[brow][bcol] = b4;
        __syncthreads();

        #pragma unroll
        for (int k = 0; k < BK; k++) {
            float ar[8], br[8];
            *(float4*)&ar[0] = *(const float4*)&As[k][trow];
            *(float4*)&ar[4] = *(const float4*)&As[k][trow + 4];
            *(float4*)&br[0] = *(const float4*)&Bs[k][tcol];
            *(float4*)&br[4] = *(const float4*)&Bs[k][tcol + 4];
            #pragma unroll
            for (int i = 0; i < 8; i++)
                #pragma unroll
                for (int j = 0; j < 8; j++)
                    acc[i][j] += ar[i] * br[j];
        }
        __syncthreads();
        Aptr += BK;
        Bptr += (size_t)BK * Nn;
    }

    #pragma unroll
    for (int i = 0; i < 8; i++) {
        float* crow = C + (size_t)(bm + trow + i) * Nn + bn + tcol;
        if (bias != nullptr) {
            #pragma unroll
            for (int j = 0; j < 8; j += 4) {
                float4 r;
                r.x = acc[i][j + 0] + bias[bn + tcol + j + 0];
                r.y = acc[i][j + 1] + bias[bn + tcol + j + 1];
                r.z = acc[i][j + 2] + bias[bn + tcol + j + 2];
                r.w = acc[i][j + 3] + bias[bn + tcol + j + 3];
                *(float4*)&crow[j] = r;
            }
        } else {
            #pragma unroll
            for (int j = 0; j < 8; j += 4) {
                float4 r;
                r.x = acc[i][j + 0]; r.y = acc[i][j + 1];
                r.z = acc[i][j + 2]; r.w = acc[i][j + 3];
                *(float4*)&crow[j] = r;
            }
        }
    }
}

// bias_comb init: bias[h] = b_gs[h]
__global__ void bias_init_kernel(const float* __restrict__ b_gs,
                                 float* __restrict__ bias) {
    int h = blockIdx.x * blockDim.x + threadIdx.x;
    if (h < H_) bias[h] = b_gs[h];
}

// bias_comb accumulate: bias[h] += sum_k b_g[k] * W_gs[k,h]  (split-K atomics)
__global__ void bias_acc_kernel(const float* __restrict__ b_g,
                                const float* __restrict__ W_gs,
                                float* __restrict__ bias) {
    int h = blockIdx.x * blockDim.x + threadIdx.x;   // 4 x 256 = 1024
    int k0 = blockIdx.y * 256;                       // 16 chunks of 256
    float acc = 0.f;
    #pragma unroll 4
    for (int k = k0; k < k0 + 256; k++)
        acc += b_g[k] * W_gs[(size_t)k * H_ + h];
    atomicAdd(&bias[h], acc);
}

// scores[row] = sum_a v[a] * tanh(epre[row,a] + sproj[b,a] + cov[row]*Wc[a])
__global__ __launch_bounds__(256) void scores_kernel(
    const float* __restrict__ epre, const float* __restrict__ sproj,
    const float* __restrict__ cov, const float* __restrict__ Wc,
    const float* __restrict__ v, float* __restrict__ scores)
{
    const int row = blockIdx.x;           // 0..6271
    const int b = row / N_;
    const float c = cov[row];
    const float* erow = epre + (size_t)row * A_;
    const float* srow = sproj + (size_t)b * A_;

    float partial = 0.f;
    for (int a = threadIdx.x; a < A_; a += 256)
        partial += v[a] * tanhf(erow[a] + srow[a] + c * Wc[a]);

    __shared__ float red[256];
    red[threadIdx.x] = partial;
    __syncthreads();
    #pragma unroll
    for (int s = 128; s > 0; s >>= 1) {
        if (threadIdx.x < s) red[threadIdx.x] += red[threadIdx.x + s];
        __syncthreads();
    }
    if (threadIdx.x == 0) scores[row] = red[0];
}

// softmax over N=49 regions + context c[b,h] = sum_n alpha[n] * gstar[b,n,h]
__global__ __launch_bounds__(256) void context_kernel(
    const float* __restrict__ scores, const float* __restrict__ gstar,
    float* __restrict__ out)
{
    const int b = blockIdx.x;
    __shared__ float alpha[N_];
    const int tid = threadIdx.x;

    if (tid == 0) {
        float m = -1e30f;
        #pragma unroll
        for (int n = 0; n < N_; n++) m = fmaxf(m, scores[b * N_ + n]);
        float s = 0.f;
        #pragma unroll
        for (int n = 0; n < N_; n++) {
            float e = expf(scores[b * N_ + n] - m);
            alpha[n] = e;
            s += e;
        }
        float inv = 1.f / s;
        #pragma unroll
        for (int n = 0; n < N_; n++) alpha[n] *= inv;
    }
    __syncthreads();

    const float* gb = gstar + (size_t)b * N_ * H_;
    for (int h = tid; h < H_; h += 256) {
        float acc = 0.f;
        #pragma unroll
        for (int n = 0; n < N_; n++)
            acc += alpha[n] * gb[(size_t)n * H_ + h];
        out[(size_t)b * H_ + h] = acc;
    }
}

// ---------------------------------------------------------------------------
extern "C" void kernel_launch(void* const* d_in, const int* in_sizes, int n_in,
                              void* d_out, int out_size) {
    const float* X    = (const float*)d_in[0];   // [128,49,4096]
    const float* s_t  = (const float*)d_in[1];   // [128,1024]
    const float* cov  = (const float*)d_in[2];   // [128,49,1]
    const float* W_g  = (const float*)d_in[3];   // [4096,4096]
    const float* b_g  = (const float*)d_in[4];   // [4096]
    const float* W_gs = (const float*)d_in[5];   // [4096,1024]
    const float* b_gs = (const float*)d_in[6];   // [1024]
    const float* W_h  = (const float*)d_in[7];   // [1024,1024]
    const float* W_s  = (const float*)d_in[8];   // [1024,1024]
    const float* W_c  = (const float*)d_in[9];   // [1,1024]
    const float* v    = (const float*)d_in[10];  // [1024]
    float* out = (float*)d_out;                  // [128,1024]

    float *Wcomb, *biascomb, *gstar, *epre, *sproj, *scores;
    cudaGetSymbolAddress((void**)&Wcomb,    g_Wcomb);
    cudaGetSymbolAddress((void**)&biascomb, g_biascomb);
    cudaGetSymbolAddress((void**)&gstar,    g_gstar);
    cudaGetSymbolAddress((void**)&epre,     g_epre);
    cudaGetSymbolAddress((void**)&sproj,    g_sproj);
    cudaGetSymbolAddress((void**)&scores,   g_scores);

    dim3 blk(256);

    // 1. W_comb = W_g @ W_gs            [4096,1024] K=4096
    sgemm_kernel<<<dim3(H_ / 128, G_ / 128), blk>>>(W_g, W_gs, nullptr, Wcomb,
                                                    G_, H_, G_);
    // 2. bias_comb = b_g @ W_gs + b_gs
    bias_init_kernel<<<H_ / 256, 256>>>(b_gs, biascomb);
    bias_acc_kernel<<<dim3(H_ / 256, G_ / 256), 256>>>(b_g, W_gs, biascomb);

    // 3. g_star = X @ W_comb + bias_comb   [6272,1024] K=4096
    sgemm_kernel<<<dim3(H_ / 128, BN_ / 128), blk>>>(X, Wcomb, biascomb, gstar,
                                                     BN_, H_, G_);
    // 4. s_proj = s_t @ W_s             [128,1024] K=1024
    sgemm_kernel<<<dim3(A_ / 128, B_ / 128), blk>>>(s_t, W_s, nullptr, sproj,
                                                    B_, A_, H_);
    // 5. e_pre = g_star @ W_h           [6272,1024] K=1024
    sgemm_kernel<<<dim3(A_ / 128, BN_ / 128), blk>>>(gstar, W_h, nullptr, epre,
                                                     BN_, A_, H_);
    // 6. scores
    scores_kernel<<<BN_, 256>>>(epre, sproj, cov, W_c, v, scores);
    // 7. softmax + context
    context_kernel<<<B_, 256>>>(scores, gstar, out);
}

// round 3
// speedup vs baseline: 3.2167x; 3.2167x over previous
#include <cuda_runtime.h>
#include <math.h>
#include <stdint.h>

// ===========================================================================
// img_attention via warp-level TF32 mma.sync (compute_103-safe; no "a" features)
//   c_img = softmax(v . tanh(Wh g* + Ws s + Wc cov)) @ g*
//   g*    = X @ (W_g @ W_gs) + (b_g @ W_gs + b_gs)      [algebraic fold]
// All GEMMs: D[m,n] = sum_k A[m,k] * Bt[n,k]  (both operands K-major)
// ===========================================================================

#define B_   128
#define N_   49
#define G_   4096
#define H_   1024
#define A_   1024
#define BN_  (B_ * N_)   // 6272

__device__ float g_WcombT[H_ * G_];     // [1024,4096] = (W_g @ W_gs)^T
__device__ float g_biascomb[H_];
__device__ float g_gstar[BN_ * H_];     // [6272,1024]
__device__ float g_epre[BN_ * A_];      // [6272,1024]; holds WgsT early
__device__ float g_WhT[A_ * H_];
__device__ float g_WsT[A_ * H_];
__device__ float g_sproj[B_ * A_];
__device__ float g_scores[BN_];

// ---------------------------------------------------------------------------
__device__ __forceinline__ uint32_t smem_u32(const void* p) {
    uint32_t a;
    asm("{ .reg .u64 t; cvta.to.shared.u64 t, %1; cvt.u32.u64 %0, t; }"
        : "=r"(a) : "l"(p));
    return a;
}
__device__ __forceinline__ float to_tf32(float x) {
    uint32_t u;
    asm("cvt.rna.tf32.f32 %0, %1;" : "=r"(u) : "f"(x));
    return __uint_as_float(u);
}
__device__ __forceinline__ void ldsm4(uint32_t* r, uint32_t addr) {
    asm volatile("ldmatrix.sync.aligned.m8n8.x4.shared.b16 {%0,%1,%2,%3}, [%4];"
                 : "=r"(r[0]), "=r"(r[1]), "=r"(r[2]), "=r"(r[3]) : "r"(addr));
}
__device__ __forceinline__ void mma_tf32(float* d, const uint32_t* a,
                                         const uint32_t* b) {
    asm volatile(
        "mma.sync.aligned.m16n8k8.row.col.f32.tf32.tf32.f32 "
        "{%0,%1,%2,%3}, {%4,%5,%6,%7}, {%8,%9}, {%0,%1,%2,%3};"
        : "+f"(d[0]), "+f"(d[1]), "+f"(d[2]), "+f"(d[3])
        : "r"(a[0]), "r"(a[1]), "r"(a[2]), "r"(a[3]), "r"(b[0]), "r"(b[1]));
}

// ---------------------------------------------------------------------------
// TF32 mma.sync GEMM: D[M,Nn] = A[M,K] @ Bt[Nn,K]^T (+ bias[Nn])
// Tile 128x128, BK=32, 256 threads (8 warps, 2x4, warp tile 64x32),
// double-buffered smem (2 x 32KB). Requires M%128==0, Nn%128==0, K%32==0.
// ---------------------------------------------------------------------------
#define TCSM (2 * 32768)

__global__ __launch_bounds__(256, 2)
void mma_gemm(const float* __restrict__ A, const float* __restrict__ Bt,
              const float* __restrict__ bias, float* __restrict__ C,
              int M, int Nn, int K)
{
    extern __shared__ char smem[];
    const uint32_t sb = smem_u32(smem);
    const int tid = threadIdx.x;
    const int lane = tid & 31;
    const int wid = tid >> 5;
    const int wr = wid >> 2;        // 0..1  (64-row band)
    const int wc = wid & 3;         // 0..3  (32-col band)
    const int bm = blockIdx.y * 128;
    const int bn = blockIdx.x * 128;

    // --- global staging: 128x32 floats per operand; 4 float4 per thread each
    const int grow = tid >> 3;              // 0..31 base row
    const int gc4  = tid & 7;               // float4 index within 32-float row
    const float* pA0 = A  + (size_t)(bm + grow) * K + gc4 * 4;
    const float* pB0 = Bt + (size_t)(bn + grow) * K + gc4 * 4;
    const size_t strideJ = (size_t)32 * K;  // +32 rows
    // swizzled byte offset (row advances by 32 per j -> row&7 unchanged)
    const uint32_t soff0 = (uint32_t)grow * 128 + ((gc4 ^ (grow & 7)) << 4);

    // --- ldmatrix base addresses
    const int aRow = wr * 64 + ((lane >> 3) & 1) * 8 + (lane & 7);
    const int cbA  = lane >> 4;                 // chunk bit (0/1)
    const uint32_t aBase = (uint32_t)aRow * 128;
    const int rmA = aRow & 7;
    const int bRow = wc * 32 + (lane >> 4) * 8 + (lane & 7);
    const int cbB  = (lane >> 3) & 1;
    const uint32_t bBase = (uint32_t)bRow * 128;
    const int rmB = bRow & 7;

    float acc[4][4][4];
    #pragma unroll
    for (int i = 0; i < 4; i++)
        #pragma unroll
        for (int j = 0; j < 4; j++)
            #pragma unroll
            for (int k = 0; k < 4; k++) acc[i][j][k] = 0.f;

    float4 sa[4], sbv[4];

#define LOADG(k0) {                                                           \
    _Pragma("unroll") for (int j = 0; j < 4; j++) {                           \
        sa[j]  = *(const float4*)(pA0 + j * strideJ + (k0));                  \
        sbv[j] = *(const float4*)(pB0 + j * strideJ + (k0));                  \
    } }

#define STST(stoff) {                                                         \
    _Pragma("unroll") for (int j = 0; j < 4; j++) {                           \
        float4 v = sa[j];                                                     \
        v.x = to_tf32(v.x); v.y = to_tf32(v.y);                               \
        v.z = to_tf32(v.z); v.w = to_tf32(v.w);                               \
        *(float4*)(smem + (stoff) + soff0 + j * 4096) = v;                    \
        float4 w = sbv[j];                                                    \
        w.x = to_tf32(w.x); w.y = to_tf32(w.y);                               \
        w.z = to_tf32(w.z); w.w = to_tf32(w.w);                               \
        *(float4*)(smem + (stoff) + 16384 + soff0 + j * 4096) = w;            \
    } }

    const int nch = K >> 5;
    LOADG(0);
    STST(0);

    for (int c = 0; c < nch; c++) {
        if (c + 1 < nch) LOADG((c + 1) * 32);
        __syncthreads();
        if (c + 1 < nch) STST(((c + 1) & 1) * 32768);

        const uint32_t As = sb + (c & 1) * 32768;
        const uint32_t Bs = As + 16384;
        #pragma unroll
        for (int kc = 0; kc < 4; kc++) {
            uint32_t afr[4][4], bfr[4][2];
            #pragma unroll
            for (int fm = 0; fm < 4; fm++)
                ldsm4(afr[fm],
                      As + fm * 2048 + aBase + ((((kc * 2) + cbA) ^ rmA) << 4));
            #pragma unroll
            for (int p = 0; p < 2; p++) {
                uint32_t t[4];
                ldsm4(t, Bs + p * 2048 + bBase + ((((kc * 2) + cbB) ^ rmB) << 4));
                bfr[2 * p][0]     = t[0]; bfr[2 * p][1]     = t[1];
                bfr[2 * p + 1][0] = t[2]; bfr[2 * p + 1][1] = t[3];
            }
            #pragma unroll
            for (int fm = 0; fm < 4; fm++)
                #pragma unroll
                for (int fn = 0; fn < 4; fn++)
                    mma_tf32(acc[fm][fn], afr[fm], bfr[fn]);
        }
    }

    // --- epilogue
    const int gid = lane >> 2, tig = lane & 3;
    #pragma unroll
    for (int fm = 0; fm < 4; fm++) {
        const int row = bm + wr * 64 + fm * 16 + gid;
        #pragma unroll
        for (int fn = 0; fn < 4; fn++) {
            const int col = bn + wc * 32 + fn * 8 + tig * 2;
            float b0 = 0.f, b1 = 0.f;
            if (bias != nullptr) { b0 = bias[col]; b1 = bias[col + 1]; }
            float2 v01, v23;
            v01.x = acc[fm][fn][0] + b0; v01.y = acc[fm][fn][1] + b1;
            v23.x = acc[fm][fn][2] + b0; v23.y = acc[fm][fn][3] + b1;
            *(float2*)(C + (size_t)row * Nn + col) = v01;
            *(float2*)(C + (size_t)(row + 8) * Nn + col) = v23;
        }
    }
#undef LOADG
#undef STST
}

// ---------------------------------------------------------------------------
// transpose: out[C,R] = in[R,C]^T   (R,C multiples of 32)
// ---------------------------------------------------------------------------
__global__ __launch_bounds__(256) void transpose_kernel(
    const float* __restrict__ in, float* __restrict__ out, int R, int C)
{
    __shared__ float t[32][33];
    const int c0 = blockIdx.x * 32, r0 = blockIdx.y * 32;
    const int x = threadIdx.x, y = threadIdx.y;
    #pragma unroll
    for (int j = 0; j < 32; j += 8)
        t[y + j][x] = in[(size_t)(r0 + y + j) * C + c0 + x];
    __syncthreads();
    #pragma unroll
    for (int j = 0; j < 32; j += 8)
        out[(size_t)(c0 + y + j) * R + r0 + x] = t[x][y + j];
}

// bias_comb = b_g @ W_gs + b_gs
__global__ void bias_init_kernel(const float* __restrict__ b_gs,
                                 float* __restrict__ bias) {
    int h = blockIdx.x * blockDim.x + threadIdx.x;
    if (h < H_) bias[h] = b_gs[h];
}
__global__ void bias_acc_kernel(const float* __restrict__ b_g,
                                const float* __restrict__ W_gs,
                                float* __restrict__ bias) {
    int h = blockIdx.x * blockDim.x + threadIdx.x;
    int k0 = blockIdx.y * 256;
    float acc = 0.f;
    #pragma unroll 4
    for (int k = k0; k < k0 + 256; k++)
        acc += b_g[k] * W_gs[(size_t)k * H_ + h];
    atomicAdd(&bias[h], acc);
}

// scores[row] = sum_a v[a] * tanh(epre[row,a] + sproj[b,a] + cov[row]*Wc[a])
__global__ __launch_bounds__(256) void scores_kernel(
    const float* __restrict__ epre, const float* __restrict__ sproj,
    const float* __restrict__ cov, const float* __restrict__ Wc,
    const float* __restrict__ v, float* __restrict__ scores)
{
    const int row = blockIdx.x;
    const int b = row / N_;
    const float c = cov[row];
    const float* erow = epre + (size_t)row * A_;
    const float* srow = sproj + (size_t)b * A_;

    float partial = 0.f;
    for (int a = threadIdx.x; a < A_; a += 256)
        partial += v[a] * tanhf(erow[a] + srow[a] + c * Wc[a]);

    __shared__ float red[256];
    red[threadIdx.x] = partial;
    __syncthreads();
    #pragma unroll
    for (int s = 128; s > 0; s >>= 1) {
        if (threadIdx.x < s) red[threadIdx.x] += red[threadIdx.x + s];
        __syncthreads();
    }
    if (threadIdx.x == 0) scores[row] = red[0];
}

// softmax over N=49 + context c[b,h] = sum_n alpha[n] * gstar[b,n,h]
__global__ __launch_bounds__(256) void context_kernel(
    const float* __restrict__ scores, const float* __restrict__ gstar,
    float* __restrict__ out)
{
    const int b = blockIdx.x;
    __shared__ float alpha[N_];
    const int tid = threadIdx.x;

    if (tid == 0) {
        float m = -1e30f;
        #pragma unroll
        for (int n = 0; n < N_; n++) m = fmaxf(m, scores[b * N_ + n]);
        float s = 0.f;
        #pragma unroll
        for (int n = 0; n < N_; n++) {
            float e = expf(scores[b * N_ + n] - m);
            alpha[n] = e;
            s += e;
        }
        float inv = 1.f / s;
        #pragma unroll
        for (int n = 0; n < N_; n++) alpha[n] *= inv;
    }
    __syncthreads();

    const float* gb = gstar + (size_t)b * N_ * H_;
    for (int h = tid; h < H_; h += 256) {
        float acc = 0.f;
        #pragma unroll
        for (int n = 0; n < N_; n++)
            acc += alpha[n] * gb[(size_t)n * H_ + h];
        out[(size_t)b * H_ + h] = acc;
    }
}

// ---------------------------------------------------------------------------
extern "C" void kernel_launch(void* const* d_in, const int* in_sizes, int n_in,
                              void* d_out, int out_size) {
    const float* X    = (const float*)d_in[0];   // [6272,4096]
    const float* s_t  = (const float*)d_in[1];   // [128,1024]
    const float* cov  = (const float*)d_in[2];   // [6272]
    const float* W_g  = (const float*)d_in[3];   // [4096,4096]
    const float* b_g  = (const float*)d_in[4];   // [4096]
    const float* W_gs = (const float*)d_in[5];   // [4096,1024]
    const float* b_gs = (const float*)d_in[6];   // [1024]
    const float* W_h  = (const float*)d_in[7];   // [1024,1024]
    const float* W_s  = (const float*)d_in[8];   // [1024,1024]
    const float* W_c  = (const float*)d_in[9];   // [1024]
    const float* v    = (const float*)d_in[10];  // [1024]
    float* out = (float*)d_out;                  // [128,1024]

    float *WcombT, *biascomb, *gstar, *epre, *WhT, *WsT, *sproj, *scores;
    cudaGetSymbolAddress((void**)&WcombT,   g_WcombT);
    cudaGetSymbolAddress((void**)&biascomb, g_biascomb);
    cudaGetSymbolAddress((void**)&gstar,    g_gstar);
    cudaGetSymbolAddress((void**)&epre,     g_epre);
    cudaGetSymbolAddress((void**)&WhT,      g_WhT);
    cudaGetSymbolAddress((void**)&WsT,      g_WsT);
    cudaGetSymbolAddress((void**)&sproj,    g_sproj);
    cudaGetSymbolAddress((void**)&scores,   g_scores);

    cudaFuncSetAttribute(mma_gemm, cudaFuncAttributeMaxDynamicSharedMemorySize,
                         TCSM);

    float* WgsT = epre;   // [1024,4096] lives in g_epre until WcombT is done

    dim3 tb(32, 8);
    transpose_kernel<<<dim3(H_ / 32, G_ / 32), tb>>>(W_gs, WgsT, G_, H_);
    transpose_kernel<<<dim3(A_ / 32, H_ / 32), tb>>>(W_h, WhT, H_, A_);
    transpose_kernel<<<dim3(A_ / 32, H_ / 32), tb>>>(W_s, WsT, H_, A_);

    bias_init_kernel<<<H_ / 256, 256>>>(b_gs, biascomb);
    bias_acc_kernel<<<dim3(H_ / 256, G_ / 256), 256>>>(b_g, W_gs, biascomb);

    // WcombT[h,g] = sum_k WgsT[h,k] * W_g[g,k]   (M=1024, N=4096, K=4096)
    mma_gemm<<<dim3(G_ / 128, H_ / 128), 256, TCSM>>>(
        WgsT, W_g, nullptr, WcombT, H_, G_, G_);

    // g_star[m,h] = sum_k X[m,k] * WcombT[h,k] + bias[h]
    mma_gemm<<<dim3(H_ / 128, BN_ / 128), 256, TCSM>>>(
        X, WcombT, biascomb, gstar, BN_, H_, G_);

    // s_proj[b,a] = sum_h s_t[b,h] * WsT[a,h]
    mma_gemm<<<dim3(A_ / 128, B_ / 128), 256, TCSM>>>(
        s_t, WsT, nullptr, sproj, B_, A_, H_);

    // e_pre[m,a] = sum_h gstar[m,h] * WhT[a,h]
    mma_gemm<<<dim3(A_ / 128, BN_ / 128), 256, TCSM>>>(
        gstar, WhT, nullptr, epre, BN_, A_, H_);

    scores_kernel<<<BN_, 256>>>(epre, sproj, cov, W_c, v, scores);
    context_kernel<<<B_, 256>>>(scores, gstar, out);
}